// round 2
// baseline (speedup 1.0000x reference)
#include <cuda_runtime.h>
#include <cuda_bf16.h>

// Problem constants
#define NA     100000   // atoms
#define NBND   200000   // bonds
#define MAXNB  6
#define AF     133      // atom fdim
#define BF     147      // bond fdim
#define HID    300      // hidden
#define NM     8192     // molecules

typedef unsigned long long u64;

// Scratch (device globals — allocation-free per harness rules)
__device__ float g_inp [NBND * HID];   // pre-activation bond messages
__device__ float g_bufA[NBND * HID];   // message ping
__device__ float g_bufB[NBND * HID];   // message pong
__device__ float g_amsg[NA   * HID];   // per-atom summed neighbor messages
__device__ float g_hid [NA   * HID];   // atom hiddens

// packed fp32x2 FMA (Blackwell; ptxas never emits this from C++)
#define FMA_F32X2(d, a, b, c) \
    asm("fma.rn.f32x2 %0, %1, %2, %3;" : "=l"(d) : "l"(a), "l"(b), "l"(c))

__device__ __forceinline__ float u64_lo(u64 v) {
    return __uint_as_float((unsigned)(v & 0xffffffffull));
}
__device__ __forceinline__ float u64_hi(u64 v) {
    return __uint_as_float((unsigned)(v >> 32));
}

// ---------------------------------------------------------------------------
// GEMM: C[M,N=300] = act( A[M,K] @ B[K,300] (+add) )
// MODE 0: A plain [M,K]
// MODE 1: A = concat(f_atoms[M,133], A2[M,300]) along K (K=433)
// MODE 2: A[r][k] = A[b2a[r]][k] - A2[b2revb[r]][k]   (fused message-pass pre)
// EPI  0: C = val ; C2 = relu(val)
// EPI  1: C = relu(val + addsrc[row,col])
// EPI  2: C = relu(val + addsrc[col])
// Tiling: BM=128, BN=64, BK=16, 256 threads, (4 row-pairs x 4 cols) FFMA2 tile.
// ---------------------------------------------------------------------------
#define BM  128
#define BN  64
#define BK  16
#define AP  132          // padded A-tile row (k-major), multiple of 4 for b64 loads
#define BN2 128          // duplicated B row: Bs2[k][2n] = Bs2[k][2n+1] = B[k][n]

template<int MODE, int EPI>
__global__ __launch_bounds__(256)
void gemm_kernel(const float* __restrict__ A, const float* __restrict__ A2,
                 const float* __restrict__ Bw, const float* __restrict__ addsrc,
                 const int* __restrict__ idx1, const int* __restrict__ idx2,
                 float* __restrict__ C, float* __restrict__ C2,
                 int M, int K)
{
    const int N = HID;
    __shared__ __align__(16) float As [BK * AP];    // As[k][m]
    __shared__ __align__(16) float Bs2[BK * BN2];   // Bs2[k][2n..2n+1] duplicated

    const int tid = threadIdx.x;          // 0..255
    const int tx  = tid & 15;             // 4 cols each
    const int ty  = tid >> 4;             // 8 rows each (4 row-pairs)
    const int row0 = blockIdx.y * BM;
    const int col0 = blockIdx.x * BN;

    // Hoist gather indices for this thread's 8 A-tile rows (MODE 2 only)
    int pia[8], pir[8];
    if (MODE == 2) {
#pragma unroll
        for (int i = 0; i < 8; i++) {
            int gr = row0 + (((tid + i * 256)) >> 4);
            int g  = (gr < M) ? gr : 0;
            pia[i] = idx1[g];
            pir[i] = idx2[g];
        }
    }

    u64 acc2[4][4];
#pragma unroll
    for (int i = 0; i < 4; i++)
#pragma unroll
        for (int j = 0; j < 4; j++) acc2[i][j] = 0ull;

    for (int k0 = 0; k0 < K; k0 += BK) {
        // --- A tile: BM x BK = 2048 elems, 8 per thread ---
#pragma unroll
        for (int i = 0; i < 8; i++) {
            int e = tid + i * 256;
            int r = e >> 4;          // 0..127
            int c = e & 15;          // 0..15
            int gr = row0 + r;
            int gk = k0 + c;
            float v = 0.f;
            if (gr < M && gk < K) {
                if (MODE == 0)      v = A[gr * K + gk];
                else if (MODE == 1) v = (gk < AF) ? A[gr * AF + gk]
                                                  : A2[gr * HID + (gk - AF)];
                else                v = A[pia[i] * HID + gk] - A2[pir[i] * HID + gk];
            }
            As[c * AP + r] = v;
        }
        // --- B tile (duplicated): BK x BN = 1024 elems, 4 per thread ---
#pragma unroll
        for (int i = 0; i < 4; i++) {
            int e = tid + i * 256;
            int r = e >> 6;          // 0..15
            int c = e & 63;          // 0..63
            int gk = k0 + r;
            int gc = col0 + c;
            float v = 0.f;
            if (gk < K && gc < N) v = Bw[gk * N + gc];
            float2 d2; d2.x = v; d2.y = v;
            *(float2*)&Bs2[r * BN2 + 2 * c] = d2;
        }
        __syncthreads();

#pragma unroll
        for (int kk = 0; kk < BK; kk++) {
            const ulonglong2 a01 = *(const ulonglong2*)&As [kk * AP  + ty * 8];
            const ulonglong2 a23 = *(const ulonglong2*)&As [kk * AP  + ty * 8 + 4];
            const ulonglong2 b01 = *(const ulonglong2*)&Bs2[kk * BN2 + tx * 8];
            const ulonglong2 b23 = *(const ulonglong2*)&Bs2[kk * BN2 + tx * 8 + 4];
            u64 ap[4] = {a01.x, a01.y, a23.x, a23.y};   // row pairs {a[2i],a[2i+1]}
            u64 bd[4] = {b01.x, b01.y, b23.x, b23.y};   // dup cols {b_j,b_j}
#pragma unroll
            for (int i = 0; i < 4; i++)
#pragma unroll
                for (int j = 0; j < 4; j++)
                    FMA_F32X2(acc2[i][j], ap[i], bd[j], acc2[i][j]);
        }
        __syncthreads();
    }

    // --- epilogue (float4 per row) ---
    const int gc = col0 + tx * 4;            // multiple of 4; all-in or all-out
    if (gc >= N) return;
#pragma unroll
    for (int i = 0; i < 4; i++) {
        const int grA = row0 + ty * 8 + 2 * i;
        const int grB = grA + 1;
        float4 va, vb;
        va.x = u64_lo(acc2[i][0]); va.y = u64_lo(acc2[i][1]);
        va.z = u64_lo(acc2[i][2]); va.w = u64_lo(acc2[i][3]);
        vb.x = u64_hi(acc2[i][0]); vb.y = u64_hi(acc2[i][1]);
        vb.z = u64_hi(acc2[i][2]); vb.w = u64_hi(acc2[i][3]);

        if (grA < M) {
            const int base = grA * N + gc;
            if (EPI == 0) {
                *(float4*)&C[base] = va;
                float4 r; r.x = fmaxf(va.x, 0.f); r.y = fmaxf(va.y, 0.f);
                r.z = fmaxf(va.z, 0.f); r.w = fmaxf(va.w, 0.f);
                *(float4*)&C2[base] = r;
            } else {
                float4 ad = (EPI == 1) ? *(const float4*)&addsrc[base]
                                       : *(const float4*)&addsrc[gc];
                va.x = fmaxf(va.x + ad.x, 0.f); va.y = fmaxf(va.y + ad.y, 0.f);
                va.z = fmaxf(va.z + ad.z, 0.f); va.w = fmaxf(va.w + ad.w, 0.f);
                *(float4*)&C[base] = va;
            }
        }
        if (grB < M) {
            const int base = grB * N + gc;
            if (EPI == 0) {
                *(float4*)&C[base] = vb;
                float4 r; r.x = fmaxf(vb.x, 0.f); r.y = fmaxf(vb.y, 0.f);
                r.z = fmaxf(vb.z, 0.f); r.w = fmaxf(vb.w, 0.f);
                *(float4*)&C2[base] = r;
            } else {
                float4 ad = (EPI == 1) ? *(const float4*)&addsrc[base]
                                       : *(const float4*)&addsrc[gc];
                vb.x = fmaxf(vb.x + ad.x, 0.f); vb.y = fmaxf(vb.y + ad.y, 0.f);
                vb.z = fmaxf(vb.z + ad.z, 0.f); vb.w = fmaxf(vb.w + ad.w, 0.f);
                *(float4*)&C[base] = vb;
            }
        }
    }
}

// ---------------------------------------------------------------------------
// a_message[a, h4] = sum_{j<6} message[a2b[a,j], h4]   (float4 lanes, HID/4=75)
// ---------------------------------------------------------------------------
#define H4 (HID / 4)
__global__ __launch_bounds__(256)
void gather_sum_kernel(const float* __restrict__ msg, const int* __restrict__ a2b,
                       float* __restrict__ amsg)
{
    int idx = blockIdx.x * blockDim.x + threadIdx.x;
    if (idx >= NA * H4) return;
    int a = idx / H4;
    int q = idx - a * H4;
    const int* nb = a2b + a * MAXNB;
    float4 s = make_float4(0.f, 0.f, 0.f, 0.f);
#pragma unroll
    for (int j = 0; j < MAXNB; j++) {
        float4 v = *(const float4*)&msg[nb[j] * HID + q * 4];
        s.x += v.x; s.y += v.y; s.z += v.z; s.w += v.w;
    }
    *(float4*)&amsg[a * HID + q * 4] = s;
}

// ---------------------------------------------------------------------------
// Per-molecule mean (mol_ids sorted): binary-search range, deterministic sum.
// ---------------------------------------------------------------------------
__global__ __launch_bounds__(128)
void mol_mean_kernel(const float* __restrict__ hidden, const int* __restrict__ mol_ids,
                     float* __restrict__ out)
{
    int m = blockIdx.x;
    __shared__ int s_start, s_end;
    if (threadIdx.x == 0) {
        int lo = 0, hi = NA;
        while (lo < hi) { int mid = (lo + hi) >> 1; if (mol_ids[mid] < m) lo = mid + 1; else hi = mid; }
        s_start = lo;
        hi = NA;
        while (lo < hi) { int mid = (lo + hi) >> 1; if (mol_ids[mid] < m + 1) lo = mid + 1; else hi = mid; }
        s_end = lo;
    }
    __syncthreads();
    const int start = s_start, end = s_end;
    const float inv = 1.f / fmaxf((float)(end - start), 1.f);
    int q = threadIdx.x;
    if (q >= H4) return;
    float4 s = make_float4(0.f, 0.f, 0.f, 0.f);
    for (int a = start; a < end; a++) {
        float4 v = *(const float4*)&hidden[a * HID + q * 4];
        s.x += v.x; s.y += v.y; s.z += v.z; s.w += v.w;
    }
    s.x *= inv; s.y *= inv; s.z *= inv; s.w *= inv;
    *(float4*)&out[m * HID + q * 4] = s;
}

// ---------------------------------------------------------------------------
extern "C" void kernel_launch(void* const* d_in, const int* in_sizes, int n_in,
                              void* d_out, int out_size)
{
    const float* f_atoms = (const float*)d_in[0];   // [NA, 133]
    const float* f_bonds = (const float*)d_in[1];   // [NBND, 147]
    const float* W_i     = (const float*)d_in[2];   // [147, 300]
    const float* W_h     = (const float*)d_in[3];   // [300, 300]
    const float* W_o     = (const float*)d_in[4];   // [433, 300]
    const float* b_o     = (const float*)d_in[5];   // [300]
    const int*   a2b     = (const int*)d_in[6];     // [NA, 6]
    const int*   b2a     = (const int*)d_in[7];     // [NBND]
    const int*   b2revb  = (const int*)d_in[8];     // [NBND]
    const int*   mol_ids = (const int*)d_in[9];     // [NA]
    float* out = (float*)d_out;                     // [NM, 300]

    float *inp, *bufA, *bufB, *amsg, *hid;
    cudaGetSymbolAddress((void**)&inp,  g_inp);
    cudaGetSymbolAddress((void**)&bufA, g_bufA);
    cudaGetSymbolAddress((void**)&bufB, g_bufB);
    cudaGetSymbolAddress((void**)&amsg, g_amsg);
    cudaGetSymbolAddress((void**)&hid,  g_hid);

    const dim3 blk(256);
    const dim3 grid_b((HID + BN - 1) / BN, (NBND + BM - 1) / BM);  // (5, 1563)
    const dim3 grid_a((HID + BN - 1) / BN, (NA + BM - 1) / BM);    // (5, 782)
    const int n_g = NA * H4;

    // 1) inp = f_bonds @ W_i ; msg0 = relu(inp)
    gemm_kernel<0, 0><<<grid_b, blk>>>(f_bonds, nullptr, W_i, nullptr,
                                       nullptr, nullptr, inp, bufA, NBND, BF);

    // 2) 3x message passing; pre fused into the GEMM A-tile gather
    float* cur = bufA;
    float* nxt = bufB;
    for (int d = 0; d < 3; d++) {
        gather_sum_kernel<<<(n_g + 255) / 256, blk>>>(cur, a2b, amsg);
        gemm_kernel<2, 1><<<grid_b, blk>>>(amsg, cur, W_h, inp,
                                           b2a, b2revb, nxt, nullptr, NBND, HID);
        float* t = cur; cur = nxt; nxt = t;
    }

    // 3) final neighbor sum + readout GEMM (concat A) + bias + relu
    gather_sum_kernel<<<(n_g + 255) / 256, blk>>>(cur, a2b, amsg);
    gemm_kernel<1, 2><<<grid_a, blk>>>(f_atoms, amsg, W_o, b_o,
                                       nullptr, nullptr, hid, nullptr, NA, AF + HID);

    // 4) per-molecule mean
    mol_mean_kernel<<<NM, 128>>>(hid, mol_ids, out);
}

// round 6
// speedup vs baseline: 1.9718x; 1.9718x over previous
#include <cuda_runtime.h>
#include <cuda_bf16.h>
#include <cstdint>

// Problem constants
#define NA     100000
#define NBND   200000
#define MAXNB  6
#define AF     133
#define BF     147
#define HID    300
#define NM     8192
#define NPAD   320

// Scratch (device globals)
__device__ float g_inp [NBND * HID];
__device__ float g_bufA[NBND * HID];
__device__ float g_bufB[NBND * HID];
__device__ float g_amsg[NA   * HID];
__device__ float g_hid [NA   * HID];

// Pre-split transposed weights: Wt[n][k] bf16 bits, zero-padded
__device__ unsigned short g_Wi_hi[NPAD * 160], g_Wi_lo[NPAD * 160];   // K=147 -> Kp=160
__device__ unsigned short g_Wh_hi[NPAD * 320], g_Wh_lo[NPAD * 320];   // K=300 -> Kp=320
__device__ unsigned short g_Wo_hi[NPAD * 448], g_Wo_lo[NPAD * 448];   // K=433 -> Kp=448

#define MMA16816(d, a, b) \
    asm volatile("mma.sync.aligned.m16n8k16.row.col.f32.bf16.bf16.f32 " \
        "{%0,%1,%2,%3}, {%4,%5,%6,%7}, {%8,%9}, {%0,%1,%2,%3};" \
        : "+f"((d)[0]), "+f"((d)[1]), "+f"((d)[2]), "+f"((d)[3]) \
        : "r"((a)[0]), "r"((a)[1]), "r"((a)[2]), "r"((a)[3]), \
          "r"((b)[0]), "r"((b)[1]))

// ---------------------------------------------------------------------------
// Weight split: Wt_hi/lo[n*Kp + k] = bf16_split(W[k*HID + n]), zero-padded
// ---------------------------------------------------------------------------
__global__ void wsplit_kernel(const float* __restrict__ W, unsigned short* __restrict__ hi,
                              unsigned short* __restrict__ lo, int K, int Kp)
{
    int idx = blockIdx.x * blockDim.x + threadIdx.x;
    if (idx >= NPAD * Kp) return;
    int n = idx / Kp, k = idx - n * Kp;
    float v = (n < HID && k < K) ? W[k * HID + n] : 0.f;
    __nv_bfloat16 h = __float2bfloat16(v);
    __nv_bfloat16 l = __float2bfloat16(v - __bfloat162float(h));
    hi[idx] = __bfloat16_as_ushort(h);
    lo[idx] = __bfloat16_as_ushort(l);
}

// ---------------------------------------------------------------------------
// HMMA bf16x3 GEMM: C[M,300] = act( A[M,K] @ W[K,300] (+add) )
// MODE 0: A plain [M, lda=K]
// MODE 1: A = concat(f_atoms[M,133], A2[M,300])
// MODE 2: A[r][k] = A[idx1[r]][k] - A2[idx2[r]][k]   (fused message-pass pre)
// EPI 0: C=val, C2=relu(val); EPI 1: C=relu(val+add[row,col]); EPI 2: C=relu(val+add[col])
// Block 128x64, 8 warps (4m x 2n), warp tile 32x32 = 2x4 m16n8k16, BK=32.
// ---------------------------------------------------------------------------
#define PITCH 40   // smem row pitch in halves; 20*r mod 32 -> conflict-free frag LDS

template<int MODE, int EPI>
__global__ __launch_bounds__(256)
void tgemm_kernel(const float* __restrict__ A, const float* __restrict__ A2,
                  const unsigned short* __restrict__ Whi, const unsigned short* __restrict__ Wlo,
                  const float* __restrict__ addsrc,
                  const int* __restrict__ idx1, const int* __restrict__ idx2,
                  float* __restrict__ C, float* __restrict__ C2,
                  int M, int K, int Kp)
{
    __shared__ __align__(16) unsigned short sAh[128 * PITCH];
    __shared__ __align__(16) unsigned short sAl[128 * PITCH];
    __shared__ __align__(16) unsigned short sBh[64 * PITCH];
    __shared__ __align__(16) unsigned short sBl[64 * PITCH];

    const int tid  = threadIdx.x;
    const int lane = tid & 31;
    const int w    = tid >> 5;
    const int wm   = w >> 1;       // 0..3
    const int wn   = w & 1;        // 0..1
    const int row0 = blockIdx.y * 128;
    const int col0 = blockIdx.x * 64;

    // Hoist gather indices for MODE 2 (one pair per smem A row this thread fills)
    int ia[8], ir[8];
    if (MODE == 2) {
#pragma unroll
        for (int i = 0; i < 8; i++) {
            int gr = row0 + (tid >> 4) + i * 16;
            int g  = (gr < M) ? gr : 0;
            ia[i] = idx1[g];
            ir[i] = idx2[g];
        }
    }

    float acc[2][4][4];
#pragma unroll
    for (int mt = 0; mt < 2; mt++)
#pragma unroll
        for (int nt = 0; nt < 4; nt++)
#pragma unroll
            for (int e = 0; e < 4; e++) acc[mt][nt][e] = 0.f;

    for (int k0 = 0; k0 < Kp; k0 += 32) {
        // --- A tile: 128 rows x 32 k (16 bf16-pairs/row), f32 -> hi/lo ---
#pragma unroll
        for (int i = 0; i < 8; i++) {
            int p  = tid + i * 256;     // 0..2047
            int r  = p >> 4;            // 0..127
            int pc = p & 15;            // 0..15
            int gk = k0 + 2 * pc;
            int gr = row0 + r;
            float v0 = 0.f, v1 = 0.f;
            if (gr < M) {
                if (MODE == 0) {
                    if (gk < K)     v0 = A[gr * K + gk];
                    if (gk + 1 < K) v1 = A[gr * K + gk + 1];
                } else if (MODE == 1) {
                    if (gk < K)     v0 = (gk < AF) ? A[gr * AF + gk] : A2[gr * HID + gk - AF];
                    if (gk + 1 < K) v1 = (gk + 1 < AF) ? A[gr * AF + gk + 1] : A2[gr * HID + gk + 1 - AF];
                } else {
                    if (gk < K) {
                        v0 = A[ia[i] * HID + gk]     - A2[ir[i] * HID + gk];
                        v1 = A[ia[i] * HID + gk + 1] - A2[ir[i] * HID + gk + 1];  // K=300 even, pairs never straddle
                    }
                }
            }
            __nv_bfloat16 h0 = __float2bfloat16(v0), h1 = __float2bfloat16(v1);
            __nv_bfloat16 l0 = __float2bfloat16(v0 - __bfloat162float(h0));
            __nv_bfloat16 l1 = __float2bfloat16(v1 - __bfloat162float(h1));
            uint32_t hw = (uint32_t)__bfloat16_as_ushort(h0) | ((uint32_t)__bfloat16_as_ushort(h1) << 16);
            uint32_t lw = (uint32_t)__bfloat16_as_ushort(l0) | ((uint32_t)__bfloat16_as_ushort(l1) << 16);
            *(uint32_t*)&sAh[r * PITCH + 2 * pc] = hw;
            *(uint32_t*)&sAl[r * PITCH + 2 * pc] = lw;
        }
        // --- B tile: 64 n-rows x 32 k from pre-split bf16 gmem ---
#pragma unroll
        for (int i = 0; i < 4; i++) {
            int p  = tid + i * 256;     // 0..1023
            int n  = p >> 4;            // 0..63
            int pc = p & 15;
            int gidx = (col0 + n) * Kp + k0 + 2 * pc;
            *(uint32_t*)&sBh[n * PITCH + 2 * pc] = *(const uint32_t*)&Whi[gidx];
            *(uint32_t*)&sBl[n * PITCH + 2 * pc] = *(const uint32_t*)&Wlo[gidx];
        }
        __syncthreads();

#pragma unroll
        for (int ks = 0; ks < 2; ks++) {
            const int cA = ks * 16 + (lane & 3) * 2;
            uint32_t ah[2][4], al[2][4], bh[4][2], bl[4][2];
#pragma unroll
            for (int mt = 0; mt < 2; mt++) {
                int r = wm * 32 + mt * 16 + (lane >> 2);
                ah[mt][0] = *(uint32_t*)&sAh[r * PITCH + cA];
                ah[mt][1] = *(uint32_t*)&sAh[(r + 8) * PITCH + cA];
                ah[mt][2] = *(uint32_t*)&sAh[r * PITCH + cA + 8];
                ah[mt][3] = *(uint32_t*)&sAh[(r + 8) * PITCH + cA + 8];
                al[mt][0] = *(uint32_t*)&sAl[r * PITCH + cA];
                al[mt][1] = *(uint32_t*)&sAl[(r + 8) * PITCH + cA];
                al[mt][2] = *(uint32_t*)&sAl[r * PITCH + cA + 8];
                al[mt][3] = *(uint32_t*)&sAl[(r + 8) * PITCH + cA + 8];
            }
#pragma unroll
            for (int nt = 0; nt < 4; nt++) {
                int n = wn * 32 + nt * 8 + (lane >> 2);
                bh[nt][0] = *(uint32_t*)&sBh[n * PITCH + cA];
                bh[nt][1] = *(uint32_t*)&sBh[n * PITCH + cA + 8];
                bl[nt][0] = *(uint32_t*)&sBl[n * PITCH + cA];
                bl[nt][1] = *(uint32_t*)&sBl[n * PITCH + cA + 8];
            }
#pragma unroll
            for (int mt = 0; mt < 2; mt++)
#pragma unroll
                for (int nt = 0; nt < 4; nt++) {
                    MMA16816(acc[mt][nt], ah[mt], bh[nt]);   // hi*hi
                    MMA16816(acc[mt][nt], ah[mt], bl[nt]);   // hi*lo
                    MMA16816(acc[mt][nt], al[mt], bh[nt]);   // lo*hi
                }
        }
        __syncthreads();
    }

    // --- epilogue ---
#pragma unroll
    for (int mt = 0; mt < 2; mt++) {
#pragma unroll
        for (int nt = 0; nt < 4; nt++) {
            const int gc = col0 + wn * 32 + nt * 8 + (lane & 3) * 2;
            if (gc >= HID) continue;
#pragma unroll
            for (int h = 0; h < 2; h++) {
                const int gr = row0 + wm * 32 + mt * 16 + (lane >> 2) + h * 8;
                if (gr >= M) continue;
                float v0 = acc[mt][nt][2 * h];
                float v1 = acc[mt][nt][2 * h + 1];
                const int base = gr * HID + gc;
                if (EPI == 0) {
                    float2 raw; raw.x = v0; raw.y = v1;
                    *(float2*)&C[base] = raw;
                    float2 rl; rl.x = fmaxf(v0, 0.f); rl.y = fmaxf(v1, 0.f);
                    *(float2*)&C2[base] = rl;
                } else if (EPI == 1) {
                    float2 ad = *(const float2*)&addsrc[base];
                    float2 rl; rl.x = fmaxf(v0 + ad.x, 0.f); rl.y = fmaxf(v1 + ad.y, 0.f);
                    *(float2*)&C[base] = rl;
                } else {
                    float2 ad = *(const float2*)&addsrc[gc];
                    float2 rl; rl.x = fmaxf(v0 + ad.x, 0.f); rl.y = fmaxf(v1 + ad.y, 0.f);
                    *(float2*)&C[base] = rl;
                }
            }
        }
    }
}

// ---------------------------------------------------------------------------
#define H4 (HID / 4)
__global__ __launch_bounds__(256)
void gather_sum_kernel(const float* __restrict__ msg, const int* __restrict__ a2b,
                       float* __restrict__ amsg)
{
    int idx = blockIdx.x * blockDim.x + threadIdx.x;
    if (idx >= NA * H4) return;
    int a = idx / H4;
    int q = idx - a * H4;
    const int* nb = a2b + a * MAXNB;
    float4 s = make_float4(0.f, 0.f, 0.f, 0.f);
#pragma unroll
    for (int j = 0; j < MAXNB; j++) {
        float4 v = *(const float4*)&msg[nb[j] * HID + q * 4];
        s.x += v.x; s.y += v.y; s.z += v.z; s.w += v.w;
    }
    *(float4*)&amsg[a * HID + q * 4] = s;
}

__global__ __launch_bounds__(128)
void mol_mean_kernel(const float* __restrict__ hidden, const int* __restrict__ mol_ids,
                     float* __restrict__ out)
{
    int m = blockIdx.x;
    __shared__ int s_start, s_end;
    if (threadIdx.x == 0) {
        int lo = 0, hi = NA;
        while (lo < hi) { int mid = (lo + hi) >> 1; if (mol_ids[mid] < m) lo = mid + 1; else hi = mid; }
        s_start = lo;
        hi = NA;
        while (lo < hi) { int mid = (lo + hi) >> 1; if (mol_ids[mid] < m + 1) lo = mid + 1; else hi = mid; }
        s_end = lo;
    }
    __syncthreads();
    const int start = s_start, end = s_end;
    const float inv = 1.f / fmaxf((float)(end - start), 1.f);
    int q = threadIdx.x;
    if (q >= H4) return;
    float4 s = make_float4(0.f, 0.f, 0.f, 0.f);
    for (int a = start; a < end; a++) {
        float4 v = *(const float4*)&hidden[a * HID + q * 4];
        s.x += v.x; s.y += v.y; s.z += v.z; s.w += v.w;
    }
    s.x *= inv; s.y *= inv; s.z *= inv; s.w *= inv;
    *(float4*)&out[m * HID + q * 4] = s;
}

// ---------------------------------------------------------------------------
extern "C" void kernel_launch(void* const* d_in, const int* in_sizes, int n_in,
                              void* d_out, int out_size)
{
    const float* f_atoms = (const float*)d_in[0];
    const float* f_bonds = (const float*)d_in[1];
    const float* W_i     = (const float*)d_in[2];
    const float* W_h     = (const float*)d_in[3];
    const float* W_o     = (const float*)d_in[4];
    const float* b_o     = (const float*)d_in[5];
    const int*   a2b     = (const int*)d_in[6];
    const int*   b2a     = (const int*)d_in[7];
    const int*   b2revb  = (const int*)d_in[8];
    const int*   mol_ids = (const int*)d_in[9];
    float* out = (float*)d_out;

    float *inp, *bufA, *bufB, *amsg, *hid;
    cudaGetSymbolAddress((void**)&inp,  g_inp);
    cudaGetSymbolAddress((void**)&bufA, g_bufA);
    cudaGetSymbolAddress((void**)&bufB, g_bufB);
    cudaGetSymbolAddress((void**)&amsg, g_amsg);
    cudaGetSymbolAddress((void**)&hid,  g_hid);
    unsigned short *wi_h, *wi_l, *wh_h, *wh_l, *wo_h, *wo_l;
    cudaGetSymbolAddress((void**)&wi_h, g_Wi_hi);  cudaGetSymbolAddress((void**)&wi_l, g_Wi_lo);
    cudaGetSymbolAddress((void**)&wh_h, g_Wh_hi);  cudaGetSymbolAddress((void**)&wh_l, g_Wh_lo);
    cudaGetSymbolAddress((void**)&wo_h, g_Wo_hi);  cudaGetSymbolAddress((void**)&wo_l, g_Wo_lo);

    // Split weights into transposed bf16 hi/lo (cheap)
    wsplit_kernel<<<(NPAD * 160 + 255) / 256, 256>>>(W_i, wi_h, wi_l, BF, 160);
    wsplit_kernel<<<(NPAD * 320 + 255) / 256, 256>>>(W_h, wh_h, wh_l, HID, 320);
    wsplit_kernel<<<(NPAD * 448 + 255) / 256, 256>>>(W_o, wo_h, wo_l, AF + HID, 448);

    const dim3 blk(256);
    const dim3 grid_b(5, (NBND + 127) / 128);   // (5, 1563)
    const dim3 grid_a(5, (NA + 127) / 128);     // (5, 782)
    const int n_g = NA * H4;

    // 1) inp = f_bonds @ W_i ; msg0 = relu(inp)
    tgemm_kernel<0, 0><<<grid_b, blk>>>(f_bonds, nullptr, wi_h, wi_l, nullptr,
                                        nullptr, nullptr, inp, bufA, NBND, BF, 160);

    // 2) 3x message passing (pre fused into the GEMM A-tile gather)
    float* cur = bufA;
    float* nxt = bufB;
    for (int d = 0; d < 3; d++) {
        gather_sum_kernel<<<(n_g + 255) / 256, blk>>>(cur, a2b, amsg);
        tgemm_kernel<2, 1><<<grid_b, blk>>>(amsg, cur, wh_h, wh_l, inp,
                                            b2a, b2revb, nxt, nullptr, NBND, HID, 320);
        float* t = cur; cur = nxt; nxt = t;
    }

    // 3) final neighbor sum + readout GEMM (concat A) + bias + relu
    gather_sum_kernel<<<(n_g + 255) / 256, blk>>>(cur, a2b, amsg);
    tgemm_kernel<1, 2><<<grid_a, blk>>>(f_atoms, amsg, wo_h, wo_l, b_o,
                                        nullptr, nullptr, hid, nullptr, NA, AF + HID, 448);

    // 4) per-molecule mean
    mol_mean_kernel<<<NM, 128>>>(hid, mol_ids, out);
}